// round 13
// baseline (speedup 1.0000x reference)
#include <cuda_runtime.h>
#include <cuda_fp16.h>
#include <cstdint>

// AFT-Full simplified: exp_pos_bias == 1  =>  num/den are per-(b,d) sums over t.
// out = ( sigmoid(q@WqT) * num/den ) @ WoT
// GEMMs: legacy mma.sync fp16 single-term, XOR-swizzled smem, BK=64,
// 64x128 CTA tile, 32x32 warp tile. This round: 2-stage pipeline + 64-reg
// clamp -> 4 CTAs/SM (32 warps) for cross-CTA latency hiding.

#define BB 4
#define TT 2048
#define DD 1024
#define MTOT (BB * TT)   // 8192
#define KD 1024

// ---------------- scratch (static device globals) ----------------
__device__ __half g_qh[MTOT * KD];
__device__ __half g_kh[MTOT * KD];
__device__ __half g_vh[MTOT * KD];
__device__ __half g_Wqh[DD * KD], g_Wkh[DD * KD], g_Wvh[DD * KD], g_Woh[DD * KD];
__device__ __half g_Yth[MTOT * DD];
__device__ __half g_Kph[MTOT * DD];
__device__ __half g_Vph[MTOT * DD];
__device__ float g_num[BB * DD];
__device__ float g_den[BB * DD];

// ---------------- merged fp32 -> fp16 convert, all 7 tensors ----------------
constexpr int ACT_CH = MTOT * KD / 16;   // 524288 chunks of 16 floats
constexpr int W_CH   = DD * KD / 16;     // 65536
constexpr int TOT_CH = 3 * ACT_CH + 4 * W_CH;

__global__ __launch_bounds__(256) void convert_all(
    const float* __restrict__ q, const float* __restrict__ k, const float* __restrict__ v,
    const float* __restrict__ wq, const float* __restrict__ wk,
    const float* __restrict__ wv, const float* __restrict__ wo)
{
    const int i = blockIdx.x * blockDim.x + threadIdx.x;

    if (i < BB * DD) { g_num[i] = 0.0f; g_den[i] = 0.0f; }

    const float* src;
    __half* dst;
    size_t off;
    if (i < ACT_CH)              { src = q;  dst = g_qh;  off = i; }
    else if (i < 2 * ACT_CH)     { src = k;  dst = g_kh;  off = i - ACT_CH; }
    else if (i < 3 * ACT_CH)     { src = v;  dst = g_vh;  off = i - 2 * ACT_CH; }
    else {
        int w = i - 3 * ACT_CH;
        int t = w >> 16;
        off = w & 65535;
        if (t == 0)      { src = wq; dst = g_Wqh; }
        else if (t == 1) { src = wk; dst = g_Wkh; }
        else if (t == 2) { src = wv; dst = g_Wvh; }
        else             { src = wo; dst = g_Woh; }
    }

    const float4* s4 = (const float4*)(src) + off * 4;
    float4 x0 = s4[0], x1 = s4[1], x2 = s4[2], x3 = s4[3];
    float xs[16] = {x0.x, x0.y, x0.z, x0.w, x1.x, x1.y, x1.z, x1.w,
                    x2.x, x2.y, x2.z, x2.w, x3.x, x3.y, x3.z, x3.w};
    __half h[16];
#pragma unroll
    for (int j = 0; j < 16; j++) h[j] = __float2half(xs[j]);
    uint4* d4 = (uint4*)(dst + off * 16);
    d4[0] = *(uint4*)(h);
    d4[1] = *(uint4*)(h + 8);
}

// ---------------- PTX helpers ----------------
__device__ __forceinline__ void ldsm_x4(uint32_t& r0, uint32_t& r1, uint32_t& r2, uint32_t& r3, uint32_t addr) {
    asm volatile("ldmatrix.sync.aligned.m8n8.x4.shared.b16 {%0,%1,%2,%3}, [%4];"
                 : "=r"(r0), "=r"(r1), "=r"(r2), "=r"(r3) : "r"(addr));
}
__device__ __forceinline__ void mma_f16(float* d, const uint32_t* a, const uint32_t* b) {
    asm volatile("mma.sync.aligned.m16n8k16.row.col.f32.f16.f16.f32 "
                 "{%0,%1,%2,%3}, {%4,%5,%6,%7}, {%8,%9}, {%0,%1,%2,%3};"
                 : "+f"(d[0]), "+f"(d[1]), "+f"(d[2]), "+f"(d[3])
                 : "r"(a[0]), "r"(a[1]), "r"(a[2]), "r"(a[3]), "r"(b[0]), "r"(b[1]));
}
__device__ __forceinline__ void cp16(uint32_t s, const void* g) {
    asm volatile("cp.async.cg.shared.global [%0], [%1], 16;" :: "r"(s), "l"(g));
}
__device__ __forceinline__ void cp_commit() {
    asm volatile("cp.async.commit_group;" ::: "memory");
}
template <int N>
__device__ __forceinline__ void cp_wait() {
    asm volatile("cp.async.wait_group %0;" :: "n"(N) : "memory");
}

// ---------------- tensor-core GEMM: C[M,N] = A[M,K] @ B[N,K]^T ----------------
// BM=64, BN=128, BK=64, 2-stage cp.async, 256 threads (8 warps 2x4, warp 32x32),
// 4 CTAs/SM, Swizzle<3,4,3> smem (128B rows).
// MODE 0: K/V merged -> fp16. MODE 1: Q + fused sigmoid*ratio -> Yt.
// MODE 2: out = Yt @ Wo^T -> fp32.
constexpr int BM = 64;
constexpr int BK = 64;
constexpr int NT = KD / BK;              // 16 k-tiles
constexpr int A_T = BM * BK * 2;         // 8192 B
constexpr int B_T = 128 * BK * 2;        // 16384 B
constexpr int STAGE_B = A_T + B_T;       // 24576 B
constexpr int NSTAGE = 2;
constexpr int SMEM_TOTAL = NSTAGE * STAGE_B;  // 49152 B

template <int MODE>
__global__ __launch_bounds__(256, 4) void hgemm(float* __restrict__ Cout)
{
    extern __shared__ char smem[];
    const uint32_t sb = (uint32_t)__cvta_generic_to_shared(smem);

    const __half *A, *Bh;
    __half* Ch = nullptr;
    float* C = nullptr;
    if (MODE == 0) {
        if (blockIdx.z == 0) { A = g_kh; Bh = g_Wkh; Ch = g_Kph; }
        else                 { A = g_vh; Bh = g_Wvh; Ch = g_Vph; }
    } else if (MODE == 1) {
        A = g_qh; Bh = g_Wqh;
    } else {
        A = g_Yth; Bh = g_Woh; C = Cout;
    }

    const int tid = threadIdx.x;
    const int wid = tid >> 5, lane = tid & 31;
    const int rowBase = blockIdx.y * BM;
    const int colBase = blockIdx.x * 128;

    // 8 warps: 2 (M) x 4 (N); warp tile 32x32
    const int warpM = (wid >> 2) * 32;
    const int warpN = (wid & 3) * 32;

    const int aRowL = warpM + (lane & 15);
    const int aC16  = (lane >> 4);            // 0 or 1
    const int bRowL = warpN + ((lane >> 4) << 3) + (lane & 7);
    const int bC16  = ((lane >> 3) & 1);

    float acc[2][4][4];
#pragma unroll
    for (int m = 0; m < 2; m++)
#pragma unroll
        for (int n = 0; n < 4; n++)
#pragma unroll
            for (int r = 0; r < 4; r++) acc[m][n][r] = 0.0f;

    auto fill_stage = [&](int buf, int k0) {
        const uint32_t stg = sb + buf * STAGE_B;
#pragma unroll
        for (int i = 0; i < 2; i++) {   // A: 512 chunks of 16B, 2/thread
            const int ch = tid + i * 256;
            const int r = ch >> 3, c = ch & 7;
            const uint32_t so = (uint32_t)(r * 128 + ((c ^ (r & 7)) * 16));
            cp16(stg + so, A + (size_t)(rowBase + r) * KD + k0 + c * 8);
        }
#pragma unroll
        for (int i = 0; i < 4; i++) {   // B: 1024 chunks, 4/thread
            const int ch = tid + i * 256;
            const int r = ch >> 3, c = ch & 7;
            const uint32_t so = (uint32_t)(r * 128 + ((c ^ (r & 7)) * 16));
            cp16(stg + A_T + so, Bh + (size_t)(colBase + r) * KD + k0 + c * 8);
        }
        cp_commit();
    };

    fill_stage(0, 0);
    fill_stage(1, BK);

    for (int kt = 0; kt < NT; kt++) {
        if (kt < NT - 1) cp_wait<1>(); else cp_wait<0>();
        __syncthreads();

        const uint32_t stg = sb + (kt & 1) * STAGE_B;
        const uint32_t sA = stg;
        const uint32_t sB = stg + A_T;

#pragma unroll
        for (int s = 0; s < 4; s++) {   // four k16 sub-steps per BK=64
            uint32_t a[2][4], b[4][2];
#pragma unroll
            for (int p = 0; p < 2; p++) {
                const int row = bRowL + p * 16;
                const int c16 = (s * 2 + bC16) ^ (row & 7);
                const uint32_t addr = sB + (uint32_t)(row * 128 + c16 * 16);
                ldsm_x4(b[2 * p][0], b[2 * p][1], b[2 * p + 1][0], b[2 * p + 1][1], addr);
            }
#pragma unroll
            for (int mf = 0; mf < 2; mf++) {
                const int row = aRowL + mf * 16;
                const int c16 = (s * 2 + aC16) ^ (row & 7);
                const uint32_t addr = sA + (uint32_t)(row * 128 + c16 * 16);
                ldsm_x4(a[mf][0], a[mf][1], a[mf][2], a[mf][3], addr);
            }
#pragma unroll
            for (int m = 0; m < 2; m++)
#pragma unroll
                for (int n = 0; n < 4; n++)
                    mma_f16(acc[m][n], a[m], b[n]);
        }
        __syncthreads();

        // refill the buffer we just consumed (2-stage: must be after compute)
        if (kt + 2 < NT) fill_stage(kt & 1, (kt + 2) * BK);
    }

    // ---------------- epilogue ----------------
    const int er = rowBase + warpM + (lane >> 2);
    const int ec = colBase + warpN + (lane & 3) * 2;

    if (MODE == 1) {
        const int b = rowBase >> 11;
#pragma unroll
        for (int n = 0; n < 4; n++) {
            const int c = ec + n * 8;
            const float r0 = g_num[b * DD + c]     / g_den[b * DD + c];
            const float r1 = g_num[b * DD + c + 1] / g_den[b * DD + c + 1];
#pragma unroll
            for (int m = 0; m < 2; m++) {
#pragma unroll
                for (int h = 0; h < 2; h++) {
                    const int r = er + m * 16 + h * 8;
                    float y0 = r0 / (1.0f + __expf(-acc[m][n][h * 2]));
                    float y1 = r1 / (1.0f + __expf(-acc[m][n][h * 2 + 1]));
                    *(__half2*)(g_Yth + (size_t)r * DD + c) =
                        __floats2half2_rn(y0, y1);
                }
            }
        }
    } else if (MODE == 0) {
#pragma unroll
        for (int m = 0; m < 2; m++)
#pragma unroll
            for (int n = 0; n < 4; n++) {
                const int c = ec + n * 8;
#pragma unroll
                for (int h = 0; h < 2; h++) {
                    const int r = er + m * 16 + h * 8;
                    *(__half2*)(Ch + (size_t)r * DD + c) =
                        __floats2half2_rn(acc[m][n][h * 2], acc[m][n][h * 2 + 1]);
                }
            }
    } else {
#pragma unroll
        for (int m = 0; m < 2; m++)
#pragma unroll
            for (int n = 0; n < 4; n++) {
                const int c = ec + n * 8;
#pragma unroll
                for (int h = 0; h < 2; h++) {
                    const int r = er + m * 16 + h * 8;
                    *(float2*)(C + (size_t)r * DD + c) =
                        make_float2(acc[m][n][h * 2], acc[m][n][h * 2 + 1]);
                }
            }
    }
}

// ---------------- num/den reduction (fp16 inputs) ----------------
__global__ __launch_bounds__(128) void reduce_kernel() {
    const int d  = blockIdx.x * 128 + threadIdx.x;
    const int t0 = blockIdx.y * 16;

    float num0 = 0.f, num1 = 0.f, num2 = 0.f, num3 = 0.f;
    float den0 = 0.f, den1 = 0.f, den2 = 0.f, den3 = 0.f;

#pragma unroll 4
    for (int t = t0; t < t0 + 16; t++) {
        const size_t off = (size_t)t * DD + d;
        float k0 = __half2float(g_Kph[off + (size_t)0 * TT * DD]);
        float k1 = __half2float(g_Kph[off + (size_t)1 * TT * DD]);
        float k2 = __half2float(g_Kph[off + (size_t)2 * TT * DD]);
        float k3 = __half2float(g_Kph[off + (size_t)3 * TT * DD]);
        float m = fmaxf(fmaxf(k0, k1), fmaxf(k2, k3));
        float e0 = __expf(k0 - m);
        float e1 = __expf(k1 - m);
        float e2 = __expf(k2 - m);
        float e3 = __expf(k3 - m);
        float v0 = __half2float(g_Vph[off + (size_t)0 * TT * DD]);
        float v1 = __half2float(g_Vph[off + (size_t)1 * TT * DD]);
        float v2 = __half2float(g_Vph[off + (size_t)2 * TT * DD]);
        float v3 = __half2float(g_Vph[off + (size_t)3 * TT * DD]);
        num0 = fmaf(e0, v0, num0);  den0 += e0;
        num1 = fmaf(e1, v1, num1);  den1 += e1;
        num2 = fmaf(e2, v2, num2);  den2 += e2;
        num3 = fmaf(e3, v3, num3);  den3 += e3;
    }

    atomicAdd(&g_num[0 * DD + d], num0);
    atomicAdd(&g_num[1 * DD + d], num1);
    atomicAdd(&g_num[2 * DD + d], num2);
    atomicAdd(&g_num[3 * DD + d], num3);
    atomicAdd(&g_den[0 * DD + d], den0);
    atomicAdd(&g_den[1 * DD + d], den1);
    atomicAdd(&g_den[2 * DD + d], den2);
    atomicAdd(&g_den[3 * DD + d], den3);
}

// ---------------------------------------------------------------------------
extern "C" void kernel_launch(void* const* d_in, const int* in_sizes, int n_in,
                              void* d_out, int out_size) {
    const float* q  = (const float*)d_in[0];
    const float* k  = (const float*)d_in[1];
    const float* v  = (const float*)d_in[2];
    const float* Wq = (const float*)d_in[3];
    const float* Wk = (const float*)d_in[4];
    const float* Wv = (const float*)d_in[5];
    const float* Wo = (const float*)d_in[6];
    // d_in[7] = W_bias: provably unused (exp(pos_bias - pos_bias) == 1)
    float* out = (float*)d_out;

    cudaFuncSetAttribute(hgemm<0>, cudaFuncAttributeMaxDynamicSharedMemorySize, SMEM_TOTAL);
    cudaFuncSetAttribute(hgemm<1>, cudaFuncAttributeMaxDynamicSharedMemorySize, SMEM_TOTAL);
    cudaFuncSetAttribute(hgemm<2>, cudaFuncAttributeMaxDynamicSharedMemorySize, SMEM_TOTAL);

    // all converts + num/den zeroing in one launch
    convert_all<<<TOT_CH / 256, 256>>>(q, k, v, Wq, Wk, Wv, Wo);

    // K, V projections (merged launch) -> fp16 Kph/Vph
    dim3 kvGrid(DD / 128, MTOT / BM, 2);    // (8, 128, 2)
    hgemm<0><<<kvGrid, 256, SMEM_TOTAL>>>(nullptr);

    // num/den over Kph, Vph
    dim3 redGrid(DD / 128, TT / 16);        // (8, 128)
    reduce_kernel<<<redGrid, 128>>>();

    // Q projection + fused sigmoid*num/den epilogue -> Yt (fp16)
    dim3 qGrid(DD / 128, MTOT / BM);        // (8, 128)
    hgemm<1><<<qGrid, 256, SMEM_TOTAL>>>(nullptr);

    // out = Yt @ Wo^T
    hgemm<2><<<qGrid, 256, SMEM_TOTAL>>>(out);
}

// round 14
// speedup vs baseline: 1.0525x; 1.0525x over previous
#include <cuda_runtime.h>
#include <cuda_fp16.h>
#include <cstdint>

// AFT-Full simplified: exp_pos_bias == 1  =>  num/den are per-(b,d) sums over t.
// out = ( sigmoid(q@WqT) * num/den ) @ WoT
// GEMMs: legacy mma.sync fp16 single-term, XOR-swizzled smem, BK=64, 3-stage.
// Mixed shapes by measurement: KV uses 128x128 tiles (2 CTA/SM, best traffic),
// Q and O use 64x128 tiles / 32x32 warps (3 CTA/SM, best per-kernel issue rate).

#define BB 4
#define TT 2048
#define DD 1024
#define MTOT (BB * TT)   // 8192
#define KD 1024

// ---------------- scratch (static device globals) ----------------
__device__ __half g_qh[MTOT * KD];
__device__ __half g_kh[MTOT * KD];
__device__ __half g_vh[MTOT * KD];
__device__ __half g_Wqh[DD * KD], g_Wkh[DD * KD], g_Wvh[DD * KD], g_Woh[DD * KD];
__device__ __half g_Yth[MTOT * DD];
__device__ __half g_Kph[MTOT * DD];
__device__ __half g_Vph[MTOT * DD];
__device__ float g_num[BB * DD];
__device__ float g_den[BB * DD];

// ---------------- merged fp32 -> fp16 convert, all 7 tensors ----------------
constexpr int ACT_CH = MTOT * KD / 16;   // 524288 chunks of 16 floats
constexpr int W_CH   = DD * KD / 16;     // 65536
constexpr int TOT_CH = 3 * ACT_CH + 4 * W_CH;

__global__ __launch_bounds__(256) void convert_all(
    const float* __restrict__ q, const float* __restrict__ k, const float* __restrict__ v,
    const float* __restrict__ wq, const float* __restrict__ wk,
    const float* __restrict__ wv, const float* __restrict__ wo)
{
    const int i = blockIdx.x * blockDim.x + threadIdx.x;

    if (i < BB * DD) { g_num[i] = 0.0f; g_den[i] = 0.0f; }

    const float* src;
    __half* dst;
    size_t off;
    if (i < ACT_CH)              { src = q;  dst = g_qh;  off = i; }
    else if (i < 2 * ACT_CH)     { src = k;  dst = g_kh;  off = i - ACT_CH; }
    else if (i < 3 * ACT_CH)     { src = v;  dst = g_vh;  off = i - 2 * ACT_CH; }
    else {
        int w = i - 3 * ACT_CH;
        int t = w >> 16;
        off = w & 65535;
        if (t == 0)      { src = wq; dst = g_Wqh; }
        else if (t == 1) { src = wk; dst = g_Wkh; }
        else if (t == 2) { src = wv; dst = g_Wvh; }
        else             { src = wo; dst = g_Woh; }
    }

    const float4* s4 = (const float4*)(src) + off * 4;
    float4 x0 = s4[0], x1 = s4[1], x2 = s4[2], x3 = s4[3];
    float xs[16] = {x0.x, x0.y, x0.z, x0.w, x1.x, x1.y, x1.z, x1.w,
                    x2.x, x2.y, x2.z, x2.w, x3.x, x3.y, x3.z, x3.w};
    __half h[16];
#pragma unroll
    for (int j = 0; j < 16; j++) h[j] = __float2half(xs[j]);
    uint4* d4 = (uint4*)(dst + off * 16);
    d4[0] = *(uint4*)(h);
    d4[1] = *(uint4*)(h + 8);
}

// ---------------- PTX helpers ----------------
__device__ __forceinline__ void ldsm_x4(uint32_t& r0, uint32_t& r1, uint32_t& r2, uint32_t& r3, uint32_t addr) {
    asm volatile("ldmatrix.sync.aligned.m8n8.x4.shared.b16 {%0,%1,%2,%3}, [%4];"
                 : "=r"(r0), "=r"(r1), "=r"(r2), "=r"(r3) : "r"(addr));
}
__device__ __forceinline__ void mma_f16(float* d, const uint32_t* a, const uint32_t* b) {
    asm volatile("mma.sync.aligned.m16n8k16.row.col.f32.f16.f16.f32 "
                 "{%0,%1,%2,%3}, {%4,%5,%6,%7}, {%8,%9}, {%0,%1,%2,%3};"
                 : "+f"(d[0]), "+f"(d[1]), "+f"(d[2]), "+f"(d[3])
                 : "r"(a[0]), "r"(a[1]), "r"(a[2]), "r"(a[3]), "r"(b[0]), "r"(b[1]));
}
__device__ __forceinline__ void cp16(uint32_t s, const void* g) {
    asm volatile("cp.async.cg.shared.global [%0], [%1], 16;" :: "r"(s), "l"(g));
}
__device__ __forceinline__ void cp_commit() {
    asm volatile("cp.async.commit_group;" ::: "memory");
}
template <int N>
__device__ __forceinline__ void cp_wait() {
    asm volatile("cp.async.wait_group %0;" :: "n"(N) : "memory");
}

constexpr int BK = 64;
constexpr int NT = KD / BK;              // 16 k-tiles

// =================== KV GEMM: R10 shape (128x128, 2 CTA/SM) ===================
constexpr int A_T128 = 128 * BK * 2;     // 16384 B
constexpr int STG128 = 2 * A_T128;       // 32768 B
constexpr int SMEM_KV = 3 * STG128;      // 98304 B

__global__ __launch_bounds__(256, 2) void hgemm_kv()
{
    extern __shared__ char smem[];
    const uint32_t sb = (uint32_t)__cvta_generic_to_shared(smem);

    const __half *A, *Bh;
    __half* Ch;
    if (blockIdx.z == 0) { A = g_kh; Bh = g_Wkh; Ch = g_Kph; }
    else                 { A = g_vh; Bh = g_Wvh; Ch = g_Vph; }

    const int tid = threadIdx.x;
    const int wid = tid >> 5, lane = tid & 31;
    const int rowBase = blockIdx.y * 128;
    const int colBase = blockIdx.x * 128;

    // 8 warps: 2 (M) x 4 (N); warp tile 64x32
    const int warpM = (wid >> 2) * 64;
    const int warpN = (wid & 3) * 32;

    const int aRowL = warpM + (lane & 15);
    const int aC16  = (lane >> 4);
    const int bRowL = warpN + ((lane >> 4) << 3) + (lane & 7);
    const int bC16  = ((lane >> 3) & 1);

    float acc[4][4][4];
#pragma unroll
    for (int m = 0; m < 4; m++)
#pragma unroll
        for (int n = 0; n < 4; n++)
#pragma unroll
            for (int r = 0; r < 4; r++) acc[m][n][r] = 0.0f;

    auto fill_stage = [&](int buf, int k0) {
        const uint32_t stg = sb + buf * STG128;
#pragma unroll
        for (int i = 0; i < 4; i++) {
            const int ch = tid + i * 256;
            const int r = ch >> 3, c = ch & 7;
            const uint32_t so = (uint32_t)(r * 128 + ((c ^ (r & 7)) * 16));
            cp16(stg + so, A + (size_t)(rowBase + r) * KD + k0 + c * 8);
        }
#pragma unroll
        for (int i = 0; i < 4; i++) {
            const int ch = tid + i * 256;
            const int r = ch >> 3, c = ch & 7;
            const uint32_t so = (uint32_t)(r * 128 + ((c ^ (r & 7)) * 16));
            cp16(stg + A_T128 + so, Bh + (size_t)(colBase + r) * KD + k0 + c * 8);
        }
        cp_commit();
    };

    fill_stage(0, 0);
    fill_stage(1, BK);

    for (int kt = 0; kt < NT; kt++) {
        if (kt < NT - 1) cp_wait<1>(); else cp_wait<0>();
        __syncthreads();

        if (kt + 2 < NT) fill_stage((kt + 2) % 3, (kt + 2) * BK);

        const uint32_t stg = sb + (kt % 3) * STG128;
        const uint32_t sA = stg;
        const uint32_t sB = stg + A_T128;

#pragma unroll
        for (int s = 0; s < 4; s++) {
            uint32_t a[4][4], b[4][2];
#pragma unroll
            for (int p = 0; p < 2; p++) {
                const int row = bRowL + p * 16;
                const int c16 = (s * 2 + bC16) ^ (row & 7);
                const uint32_t addr = sB + (uint32_t)(row * 128 + c16 * 16);
                ldsm_x4(b[2 * p][0], b[2 * p][1], b[2 * p + 1][0], b[2 * p + 1][1], addr);
            }
#pragma unroll
            for (int mf = 0; mf < 4; mf++) {
                const int row = aRowL + mf * 16;
                const int c16 = (s * 2 + aC16) ^ (row & 7);
                const uint32_t addr = sA + (uint32_t)(row * 128 + c16 * 16);
                ldsm_x4(a[mf][0], a[mf][1], a[mf][2], a[mf][3], addr);
            }
#pragma unroll
            for (int m = 0; m < 4; m++)
#pragma unroll
                for (int n = 0; n < 4; n++)
                    mma_f16(acc[m][n], a[m], b[n]);
        }
        __syncthreads();
    }

    const int er = rowBase + warpM + (lane >> 2);
    const int ec = colBase + warpN + (lane & 3) * 2;
#pragma unroll
    for (int m = 0; m < 4; m++)
#pragma unroll
        for (int n = 0; n < 4; n++) {
            const int c = ec + n * 8;
#pragma unroll
            for (int h = 0; h < 2; h++) {
                const int r = er + m * 16 + h * 8;
                *(__half2*)(Ch + (size_t)r * DD + c) =
                    __floats2half2_rn(acc[m][n][h * 2], acc[m][n][h * 2 + 1]);
            }
        }
}

// =============== Q/O GEMM: R12 shape (64x128, 32x32 warps, 3 CTA/SM) ===============
constexpr int A_T64 = 64 * BK * 2;       // 8192 B
constexpr int B_T64 = 128 * BK * 2;      // 16384 B
constexpr int STG64 = A_T64 + B_T64;     // 24576 B
constexpr int SMEM_QO = 3 * STG64;       // 73728 B

// MODE 1: Q + fused sigmoid*ratio -> g_Yth (fp16). MODE 2: out = Yt@Wo^T -> fp32.
template <int MODE>
__global__ __launch_bounds__(256, 3) void hgemm_qo(float* __restrict__ Cout)
{
    extern __shared__ char smem[];
    const uint32_t sb = (uint32_t)__cvta_generic_to_shared(smem);

    const __half* A  = (MODE == 1) ? g_qh  : g_Yth;
    const __half* Bh = (MODE == 1) ? g_Wqh : g_Woh;

    const int tid = threadIdx.x;
    const int wid = tid >> 5, lane = tid & 31;
    const int rowBase = blockIdx.y * 64;
    const int colBase = blockIdx.x * 128;

    // 8 warps: 2 (M) x 4 (N); warp tile 32x32
    const int warpM = (wid >> 2) * 32;
    const int warpN = (wid & 3) * 32;

    const int aRowL = warpM + (lane & 15);
    const int aC16  = (lane >> 4);
    const int bRowL = warpN + ((lane >> 4) << 3) + (lane & 7);
    const int bC16  = ((lane >> 3) & 1);

    float acc[2][4][4];
#pragma unroll
    for (int m = 0; m < 2; m++)
#pragma unroll
        for (int n = 0; n < 4; n++)
#pragma unroll
            for (int r = 0; r < 4; r++) acc[m][n][r] = 0.0f;

    auto fill_stage = [&](int buf, int k0) {
        const uint32_t stg = sb + buf * STG64;
#pragma unroll
        for (int i = 0; i < 2; i++) {
            const int ch = tid + i * 256;
            const int r = ch >> 3, c = ch & 7;
            const uint32_t so = (uint32_t)(r * 128 + ((c ^ (r & 7)) * 16));
            cp16(stg + so, A + (size_t)(rowBase + r) * KD + k0 + c * 8);
        }
#pragma unroll
        for (int i = 0; i < 4; i++) {
            const int ch = tid + i * 256;
            const int r = ch >> 3, c = ch & 7;
            const uint32_t so = (uint32_t)(r * 128 + ((c ^ (r & 7)) * 16));
            cp16(stg + A_T64 + so, Bh + (size_t)(colBase + r) * KD + k0 + c * 8);
        }
        cp_commit();
    };

    fill_stage(0, 0);
    fill_stage(1, BK);

    for (int kt = 0; kt < NT; kt++) {
        if (kt < NT - 1) cp_wait<1>(); else cp_wait<0>();
        __syncthreads();

        if (kt + 2 < NT) fill_stage((kt + 2) % 3, (kt + 2) * BK);

        const uint32_t stg = sb + (kt % 3) * STG64;
        const uint32_t sA = stg;
        const uint32_t sB = stg + A_T64;

#pragma unroll
        for (int s = 0; s < 4; s++) {
            uint32_t a[2][4], b[4][2];
#pragma unroll
            for (int p = 0; p < 2; p++) {
                const int row = bRowL + p * 16;
                const int c16 = (s * 2 + bC16) ^ (row & 7);
                const uint32_t addr = sB + (uint32_t)(row * 128 + c16 * 16);
                ldsm_x4(b[2 * p][0], b[2 * p][1], b[2 * p + 1][0], b[2 * p + 1][1], addr);
            }
#pragma unroll
            for (int mf = 0; mf < 2; mf++) {
                const int row = aRowL + mf * 16;
                const int c16 = (s * 2 + aC16) ^ (row & 7);
                const uint32_t addr = sA + (uint32_t)(row * 128 + c16 * 16);
                ldsm_x4(a[mf][0], a[mf][1], a[mf][2], a[mf][3], addr);
            }
#pragma unroll
            for (int m = 0; m < 2; m++)
#pragma unroll
                for (int n = 0; n < 4; n++)
                    mma_f16(acc[m][n], a[m], b[n]);
        }
        __syncthreads();
    }

    const int er = rowBase + warpM + (lane >> 2);
    const int ec = colBase + warpN + (lane & 3) * 2;

    if (MODE == 1) {
        const int b = rowBase >> 11;
#pragma unroll
        for (int n = 0; n < 4; n++) {
            const int c = ec + n * 8;
            const float r0 = g_num[b * DD + c]     / g_den[b * DD + c];
            const float r1 = g_num[b * DD + c + 1] / g_den[b * DD + c + 1];
#pragma unroll
            for (int m = 0; m < 2; m++) {
#pragma unroll
                for (int h = 0; h < 2; h++) {
                    const int r = er + m * 16 + h * 8;
                    float y0 = r0 / (1.0f + __expf(-acc[m][n][h * 2]));
                    float y1 = r1 / (1.0f + __expf(-acc[m][n][h * 2 + 1]));
                    *(__half2*)(g_Yth + (size_t)r * DD + c) =
                        __floats2half2_rn(y0, y1);
                }
            }
        }
    } else {
#pragma unroll
        for (int m = 0; m < 2; m++)
#pragma unroll
            for (int n = 0; n < 4; n++) {
                const int c = ec + n * 8;
#pragma unroll
                for (int h = 0; h < 2; h++) {
                    const int r = er + m * 16 + h * 8;
                    *(float2*)(Cout + (size_t)r * DD + c) =
                        make_float2(acc[m][n][h * 2], acc[m][n][h * 2 + 1]);
                }
            }
    }
}

// ---------------- num/den reduction (fp16 inputs) ----------------
__global__ __launch_bounds__(128) void reduce_kernel() {
    const int d  = blockIdx.x * 128 + threadIdx.x;
    const int t0 = blockIdx.y * 16;

    float num0 = 0.f, num1 = 0.f, num2 = 0.f, num3 = 0.f;
    float den0 = 0.f, den1 = 0.f, den2 = 0.f, den3 = 0.f;

#pragma unroll 4
    for (int t = t0; t < t0 + 16; t++) {
        const size_t off = (size_t)t * DD + d;
        float k0 = __half2float(g_Kph[off + (size_t)0 * TT * DD]);
        float k1 = __half2float(g_Kph[off + (size_t)1 * TT * DD]);
        float k2 = __half2float(g_Kph[off + (size_t)2 * TT * DD]);
        float k3 = __half2float(g_Kph[off + (size_t)3 * TT * DD]);
        float m = fmaxf(fmaxf(k0, k1), fmaxf(k2, k3));
        float e0 = __expf(k0 - m);
        float e1 = __expf(k1 - m);
        float e2 = __expf(k2 - m);
        float e3 = __expf(k3 - m);
        float v0 = __half2float(g_Vph[off + (size_t)0 * TT * DD]);
        float v1 = __half2float(g_Vph[off + (size_t)1 * TT * DD]);
        float v2 = __half2float(g_Vph[off + (size_t)2 * TT * DD]);
        float v3 = __half2float(g_Vph[off + (size_t)3 * TT * DD]);
        num0 = fmaf(e0, v0, num0);  den0 += e0;
        num1 = fmaf(e1, v1, num1);  den1 += e1;
        num2 = fmaf(e2, v2, num2);  den2 += e2;
        num3 = fmaf(e3, v3, num3);  den3 += e3;
    }

    atomicAdd(&g_num[0 * DD + d], num0);
    atomicAdd(&g_num[1 * DD + d], num1);
    atomicAdd(&g_num[2 * DD + d], num2);
    atomicAdd(&g_num[3 * DD + d], num3);
    atomicAdd(&g_den[0 * DD + d], den0);
    atomicAdd(&g_den[1 * DD + d], den1);
    atomicAdd(&g_den[2 * DD + d], den2);
    atomicAdd(&g_den[3 * DD + d], den3);
}

// ---------------------------------------------------------------------------
extern "C" void kernel_launch(void* const* d_in, const int* in_sizes, int n_in,
                              void* d_out, int out_size) {
    const float* q  = (const float*)d_in[0];
    const float* k  = (const float*)d_in[1];
    const float* v  = (const float*)d_in[2];
    const float* Wq = (const float*)d_in[3];
    const float* Wk = (const float*)d_in[4];
    const float* Wv = (const float*)d_in[5];
    const float* Wo = (const float*)d_in[6];
    // d_in[7] = W_bias: provably unused (exp(pos_bias - pos_bias) == 1)
    float* out = (float*)d_out;

    cudaFuncSetAttribute(hgemm_kv,    cudaFuncAttributeMaxDynamicSharedMemorySize, SMEM_KV);
    cudaFuncSetAttribute(hgemm_qo<1>, cudaFuncAttributeMaxDynamicSharedMemorySize, SMEM_QO);
    cudaFuncSetAttribute(hgemm_qo<2>, cudaFuncAttributeMaxDynamicSharedMemorySize, SMEM_QO);

    // all converts + num/den zeroing in one launch
    convert_all<<<TOT_CH / 256, 256>>>(q, k, v, Wq, Wk, Wv, Wo);

    // K, V projections (merged launch, 128x128 tiles) -> fp16 Kph/Vph
    dim3 kvGrid(DD / 128, MTOT / 128, 2);   // (8, 64, 2)
    hgemm_kv<<<kvGrid, 256, SMEM_KV>>>();

    // num/den over Kph, Vph
    dim3 redGrid(DD / 128, TT / 16);        // (8, 128)
    reduce_kernel<<<redGrid, 128>>>();

    // Q projection + fused sigmoid*num/den epilogue -> Yt (fp16), 64x128 tiles
    dim3 qoGrid(DD / 128, MTOT / 64);       // (8, 128)
    hgemm_qo<1><<<qoGrid, 256, SMEM_QO>>>(nullptr);

    // out = Yt @ Wo^T
    hgemm_qo<2><<<qoGrid, 256, SMEM_QO>>>(out);
}

// round 15
// speedup vs baseline: 1.0545x; 1.0019x over previous
#include <cuda_runtime.h>
#include <cuda_fp16.h>
#include <cstdint>

// AFT-Full simplified: exp_pos_bias == 1  =>  num/den are per-(b,d) sums over t.
// out = ( sigmoid(q@WqT) * num/den ) @ WoT
// GEMMs: legacy mma.sync fp16 single-term, XOR-swizzled smem, BK=64, 3-stage.
// KV: 128x128 tiles (2 CTA/SM). Q/O: 64x128 tiles, 32x32 warps (3 CTA/SM).
// This round: single barrier per mainloop iteration (end-of-loop sync proven
// redundant), half2-vectorized reduction.

#define BB 4
#define TT 2048
#define DD 1024
#define MTOT (BB * TT)   // 8192
#define KD 1024

// ---------------- scratch (static device globals) ----------------
__device__ __half g_qh[MTOT * KD];
__device__ __half g_kh[MTOT * KD];
__device__ __half g_vh[MTOT * KD];
__device__ __half g_Wqh[DD * KD], g_Wkh[DD * KD], g_Wvh[DD * KD], g_Woh[DD * KD];
__device__ __half g_Yth[MTOT * DD];
__device__ __half g_Kph[MTOT * DD];
__device__ __half g_Vph[MTOT * DD];
__device__ float g_num[BB * DD];
__device__ float g_den[BB * DD];

// ---------------- merged fp32 -> fp16 convert, all 7 tensors ----------------
constexpr int ACT_CH = MTOT * KD / 16;   // 524288 chunks of 16 floats
constexpr int W_CH   = DD * KD / 16;     // 65536
constexpr int TOT_CH = 3 * ACT_CH + 4 * W_CH;

__global__ __launch_bounds__(256) void convert_all(
    const float* __restrict__ q, const float* __restrict__ k, const float* __restrict__ v,
    const float* __restrict__ wq, const float* __restrict__ wk,
    const float* __restrict__ wv, const float* __restrict__ wo)
{
    const int i = blockIdx.x * blockDim.x + threadIdx.x;

    if (i < BB * DD) { g_num[i] = 0.0f; g_den[i] = 0.0f; }

    const float* src;
    __half* dst;
    size_t off;
    if (i < ACT_CH)              { src = q;  dst = g_qh;  off = i; }
    else if (i < 2 * ACT_CH)     { src = k;  dst = g_kh;  off = i - ACT_CH; }
    else if (i < 3 * ACT_CH)     { src = v;  dst = g_vh;  off = i - 2 * ACT_CH; }
    else {
        int w = i - 3 * ACT_CH;
        int t = w >> 16;
        off = w & 65535;
        if (t == 0)      { src = wq; dst = g_Wqh; }
        else if (t == 1) { src = wk; dst = g_Wkh; }
        else if (t == 2) { src = wv; dst = g_Wvh; }
        else             { src = wo; dst = g_Woh; }
    }

    const float4* s4 = (const float4*)(src) + off * 4;
    float4 x0 = s4[0], x1 = s4[1], x2 = s4[2], x3 = s4[3];
    float xs[16] = {x0.x, x0.y, x0.z, x0.w, x1.x, x1.y, x1.z, x1.w,
                    x2.x, x2.y, x2.z, x2.w, x3.x, x3.y, x3.z, x3.w};
    __half h[16];
#pragma unroll
    for (int j = 0; j < 16; j++) h[j] = __float2half(xs[j]);
    uint4* d4 = (uint4*)(dst + off * 16);
    d4[0] = *(uint4*)(h);
    d4[1] = *(uint4*)(h + 8);
}

// ---------------- PTX helpers ----------------
__device__ __forceinline__ void ldsm_x4(uint32_t& r0, uint32_t& r1, uint32_t& r2, uint32_t& r3, uint32_t addr) {
    asm volatile("ldmatrix.sync.aligned.m8n8.x4.shared.b16 {%0,%1,%2,%3}, [%4];"
                 : "=r"(r0), "=r"(r1), "=r"(r2), "=r"(r3) : "r"(addr));
}
__device__ __forceinline__ void mma_f16(float* d, const uint32_t* a, const uint32_t* b) {
    asm volatile("mma.sync.aligned.m16n8k16.row.col.f32.f16.f16.f32 "
                 "{%0,%1,%2,%3}, {%4,%5,%6,%7}, {%8,%9}, {%0,%1,%2,%3};"
                 : "+f"(d[0]), "+f"(d[1]), "+f"(d[2]), "+f"(d[3])
                 : "r"(a[0]), "r"(a[1]), "r"(a[2]), "r"(a[3]), "r"(b[0]), "r"(b[1]));
}
__device__ __forceinline__ void cp16(uint32_t s, const void* g) {
    asm volatile("cp.async.cg.shared.global [%0], [%1], 16;" :: "r"(s), "l"(g));
}
__device__ __forceinline__ void cp_commit() {
    asm volatile("cp.async.commit_group;" ::: "memory");
}
template <int N>
__device__ __forceinline__ void cp_wait() {
    asm volatile("cp.async.wait_group %0;" :: "n"(N) : "memory");
}

constexpr int BK = 64;
constexpr int NT = KD / BK;              // 16 k-tiles

// =================== KV GEMM: 128x128, 64x32 warps, 2 CTA/SM ===================
constexpr int A_T128 = 128 * BK * 2;     // 16384 B
constexpr int STG128 = 2 * A_T128;       // 32768 B
constexpr int SMEM_KV = 3 * STG128;      // 98304 B

__global__ __launch_bounds__(256, 2) void hgemm_kv()
{
    extern __shared__ char smem[];
    const uint32_t sb = (uint32_t)__cvta_generic_to_shared(smem);

    const __half *A, *Bh;
    __half* Ch;
    if (blockIdx.z == 0) { A = g_kh; Bh = g_Wkh; Ch = g_Kph; }
    else                 { A = g_vh; Bh = g_Wvh; Ch = g_Vph; }

    const int tid = threadIdx.x;
    const int wid = tid >> 5, lane = tid & 31;
    const int rowBase = blockIdx.y * 128;
    const int colBase = blockIdx.x * 128;

    const int warpM = (wid >> 2) * 64;
    const int warpN = (wid & 3) * 32;

    const int aRowL = warpM + (lane & 15);
    const int aC16  = (lane >> 4);
    const int bRowL = warpN + ((lane >> 4) << 3) + (lane & 7);
    const int bC16  = ((lane >> 3) & 1);

    float acc[4][4][4];
#pragma unroll
    for (int m = 0; m < 4; m++)
#pragma unroll
        for (int n = 0; n < 4; n++)
#pragma unroll
            for (int r = 0; r < 4; r++) acc[m][n][r] = 0.0f;

    auto fill_stage = [&](int buf, int k0) {
        const uint32_t stg = sb + buf * STG128;
#pragma unroll
        for (int i = 0; i < 4; i++) {
            const int ch = tid + i * 256;
            const int r = ch >> 3, c = ch & 7;
            const uint32_t so = (uint32_t)(r * 128 + ((c ^ (r & 7)) * 16));
            cp16(stg + so, A + (size_t)(rowBase + r) * KD + k0 + c * 8);
        }
#pragma unroll
        for (int i = 0; i < 4; i++) {
            const int ch = tid + i * 256;
            const int r = ch >> 3, c = ch & 7;
            const uint32_t so = (uint32_t)(r * 128 + ((c ^ (r & 7)) * 16));
            cp16(stg + A_T128 + so, Bh + (size_t)(colBase + r) * KD + k0 + c * 8);
        }
        cp_commit();
    };

    fill_stage(0, 0);
    fill_stage(1, BK);

    for (int kt = 0; kt < NT; kt++) {
        if (kt < NT - 1) cp_wait<1>(); else cp_wait<0>();
        // Single barrier per iteration: orders "everyone done reading buffer
        // (kt+2)%3 from iteration kt-1" before this iteration's fill overwrites
        // it, AND "buffer kt%3 load complete" before compute reads it.
        __syncthreads();

        if (kt + 2 < NT) fill_stage((kt + 2) % 3, (kt + 2) * BK);

        const uint32_t stg = sb + (kt % 3) * STG128;
        const uint32_t sA = stg;
        const uint32_t sB = stg + A_T128;

#pragma unroll
        for (int s = 0; s < 4; s++) {
            uint32_t a[4][4], b[4][2];
#pragma unroll
            for (int p = 0; p < 2; p++) {
                const int row = bRowL + p * 16;
                const int c16 = (s * 2 + bC16) ^ (row & 7);
                const uint32_t addr = sB + (uint32_t)(row * 128 + c16 * 16);
                ldsm_x4(b[2 * p][0], b[2 * p][1], b[2 * p + 1][0], b[2 * p + 1][1], addr);
            }
#pragma unroll
            for (int mf = 0; mf < 4; mf++) {
                const int row = aRowL + mf * 16;
                const int c16 = (s * 2 + aC16) ^ (row & 7);
                const uint32_t addr = sA + (uint32_t)(row * 128 + c16 * 16);
                ldsm_x4(a[mf][0], a[mf][1], a[mf][2], a[mf][3], addr);
            }
#pragma unroll
            for (int m = 0; m < 4; m++)
#pragma unroll
                for (int n = 0; n < 4; n++)
                    mma_f16(acc[m][n], a[m], b[n]);
        }
        // no end-of-loop barrier (redundant; see comment above)
    }

    const int er = rowBase + warpM + (lane >> 2);
    const int ec = colBase + warpN + (lane & 3) * 2;
#pragma unroll
    for (int m = 0; m < 4; m++)
#pragma unroll
        for (int n = 0; n < 4; n++) {
            const int c = ec + n * 8;
#pragma unroll
            for (int h = 0; h < 2; h++) {
                const int r = er + m * 16 + h * 8;
                *(__half2*)(Ch + (size_t)r * DD + c) =
                    __floats2half2_rn(acc[m][n][h * 2], acc[m][n][h * 2 + 1]);
            }
        }
}

// =============== Q/O GEMM: 64x128, 32x32 warps, 3 CTA/SM ===============
constexpr int A_T64 = 64 * BK * 2;       // 8192 B
constexpr int B_T64 = 128 * BK * 2;      // 16384 B
constexpr int STG64 = A_T64 + B_T64;     // 24576 B
constexpr int SMEM_QO = 3 * STG64;       // 73728 B

// MODE 1: Q + fused sigmoid*ratio -> g_Yth (fp16). MODE 2: out = Yt@Wo^T -> fp32.
template <int MODE>
__global__ __launch_bounds__(256, 3) void hgemm_qo(float* __restrict__ Cout)
{
    extern __shared__ char smem[];
    const uint32_t sb = (uint32_t)__cvta_generic_to_shared(smem);

    const __half* A  = (MODE == 1) ? g_qh  : g_Yth;
    const __half* Bh = (MODE == 1) ? g_Wqh : g_Woh;

    const int tid = threadIdx.x;
    const int wid = tid >> 5, lane = tid & 31;
    const int rowBase = blockIdx.y * 64;
    const int colBase = blockIdx.x * 128;

    const int warpM = (wid >> 2) * 32;
    const int warpN = (wid & 3) * 32;

    const int aRowL = warpM + (lane & 15);
    const int aC16  = (lane >> 4);
    const int bRowL = warpN + ((lane >> 4) << 3) + (lane & 7);
    const int bC16  = ((lane >> 3) & 1);

    float acc[2][4][4];
#pragma unroll
    for (int m = 0; m < 2; m++)
#pragma unroll
        for (int n = 0; n < 4; n++)
#pragma unroll
            for (int r = 0; r < 4; r++) acc[m][n][r] = 0.0f;

    auto fill_stage = [&](int buf, int k0) {
        const uint32_t stg = sb + buf * STG64;
#pragma unroll
        for (int i = 0; i < 2; i++) {
            const int ch = tid + i * 256;
            const int r = ch >> 3, c = ch & 7;
            const uint32_t so = (uint32_t)(r * 128 + ((c ^ (r & 7)) * 16));
            cp16(stg + so, A + (size_t)(rowBase + r) * KD + k0 + c * 8);
        }
#pragma unroll
        for (int i = 0; i < 4; i++) {
            const int ch = tid + i * 256;
            const int r = ch >> 3, c = ch & 7;
            const uint32_t so = (uint32_t)(r * 128 + ((c ^ (r & 7)) * 16));
            cp16(stg + A_T64 + so, Bh + (size_t)(colBase + r) * KD + k0 + c * 8);
        }
        cp_commit();
    };

    fill_stage(0, 0);
    fill_stage(1, BK);

    for (int kt = 0; kt < NT; kt++) {
        if (kt < NT - 1) cp_wait<1>(); else cp_wait<0>();
        __syncthreads();   // single barrier per iteration (see hgemm_kv comment)

        if (kt + 2 < NT) fill_stage((kt + 2) % 3, (kt + 2) * BK);

        const uint32_t stg = sb + (kt % 3) * STG64;
        const uint32_t sA = stg;
        const uint32_t sB = stg + A_T64;

#pragma unroll
        for (int s = 0; s < 4; s++) {
            uint32_t a[2][4], b[4][2];
#pragma unroll
            for (int p = 0; p < 2; p++) {
                const int row = bRowL + p * 16;
                const int c16 = (s * 2 + bC16) ^ (row & 7);
                const uint32_t addr = sB + (uint32_t)(row * 128 + c16 * 16);
                ldsm_x4(b[2 * p][0], b[2 * p][1], b[2 * p + 1][0], b[2 * p + 1][1], addr);
            }
#pragma unroll
            for (int mf = 0; mf < 2; mf++) {
                const int row = aRowL + mf * 16;
                const int c16 = (s * 2 + aC16) ^ (row & 7);
                const uint32_t addr = sA + (uint32_t)(row * 128 + c16 * 16);
                ldsm_x4(a[mf][0], a[mf][1], a[mf][2], a[mf][3], addr);
            }
#pragma unroll
            for (int m = 0; m < 2; m++)
#pragma unroll
                for (int n = 0; n < 4; n++)
                    mma_f16(acc[m][n], a[m], b[n]);
        }
    }

    const int er = rowBase + warpM + (lane >> 2);
    const int ec = colBase + warpN + (lane & 3) * 2;

    if (MODE == 1) {
        const int b = rowBase >> 11;
#pragma unroll
        for (int n = 0; n < 4; n++) {
            const int c = ec + n * 8;
            const float r0 = g_num[b * DD + c]     / g_den[b * DD + c];
            const float r1 = g_num[b * DD + c + 1] / g_den[b * DD + c + 1];
#pragma unroll
            for (int m = 0; m < 2; m++) {
#pragma unroll
                for (int h = 0; h < 2; h++) {
                    const int r = er + m * 16 + h * 8;
                    float y0 = r0 / (1.0f + __expf(-acc[m][n][h * 2]));
                    float y1 = r1 / (1.0f + __expf(-acc[m][n][h * 2 + 1]));
                    *(__half2*)(g_Yth + (size_t)r * DD + c) =
                        __floats2half2_rn(y0, y1);
                }
            }
        }
    } else {
#pragma unroll
        for (int m = 0; m < 2; m++)
#pragma unroll
            for (int n = 0; n < 4; n++) {
                const int c = ec + n * 8;
#pragma unroll
                for (int h = 0; h < 2; h++) {
                    const int r = er + m * 16 + h * 8;
                    *(float2*)(Cout + (size_t)r * DD + c) =
                        make_float2(acc[m][n][h * 2], acc[m][n][h * 2 + 1]);
                }
            }
    }
}

// ---------------- num/den reduction (fp16 inputs, half2 loads) ----------------
// Each thread handles 2 adjacent d's. grid = (DD/256, TT/16) = (4, 128).
__global__ __launch_bounds__(128) void reduce_kernel() {
    const int d2 = blockIdx.x * 128 + threadIdx.x;   // half2 index
    const int d  = d2 * 2;
    const int t0 = blockIdx.y * 16;

    float2 num[BB], den[BB];
#pragma unroll
    for (int b = 0; b < BB; b++) { num[b] = make_float2(0.f, 0.f); den[b] = make_float2(0.f, 0.f); }

#pragma unroll 4
    for (int t = t0; t < t0 + 16; t++) {
        const size_t off = (size_t)t * DD + d;
        float2 kk[BB], vv[BB];
#pragma unroll
        for (int b = 0; b < BB; b++) {
            kk[b] = __half22float2(*(const __half2*)(g_Kph + off + (size_t)b * TT * DD));
            vv[b] = __half22float2(*(const __half2*)(g_Vph + off + (size_t)b * TT * DD));
        }
        float mx = fmaxf(fmaxf(kk[0].x, kk[1].x), fmaxf(kk[2].x, kk[3].x));
        float my = fmaxf(fmaxf(kk[0].y, kk[1].y), fmaxf(kk[2].y, kk[3].y));
#pragma unroll
        for (int b = 0; b < BB; b++) {
            float ex = __expf(kk[b].x - mx);
            float ey = __expf(kk[b].y - my);
            num[b].x = fmaf(ex, vv[b].x, num[b].x);
            num[b].y = fmaf(ey, vv[b].y, num[b].y);
            den[b].x += ex;
            den[b].y += ey;
        }
    }

#pragma unroll
    for (int b = 0; b < BB; b++) {
        atomicAdd(&g_num[b * DD + d],     num[b].x);
        atomicAdd(&g_num[b * DD + d + 1], num[b].y);
        atomicAdd(&g_den[b * DD + d],     den[b].x);
        atomicAdd(&g_den[b * DD + d + 1], den[b].y);
    }
}

// ---------------------------------------------------------------------------
extern "C" void kernel_launch(void* const* d_in, const int* in_sizes, int n_in,
                              void* d_out, int out_size) {
    const float* q  = (const float*)d_in[0];
    const float* k  = (const float*)d_in[1];
    const float* v  = (const float*)d_in[2];
    const float* Wq = (const float*)d_in[3];
    const float* Wk = (const float*)d_in[4];
    const float* Wv = (const float*)d_in[5];
    const float* Wo = (const float*)d_in[6];
    // d_in[7] = W_bias: provably unused (exp(pos_bias - pos_bias) == 1)
    float* out = (float*)d_out;

    cudaFuncSetAttribute(hgemm_kv,    cudaFuncAttributeMaxDynamicSharedMemorySize, SMEM_KV);
    cudaFuncSetAttribute(hgemm_qo<1>, cudaFuncAttributeMaxDynamicSharedMemorySize, SMEM_QO);
    cudaFuncSetAttribute(hgemm_qo<2>, cudaFuncAttributeMaxDynamicSharedMemorySize, SMEM_QO);

    // all converts + num/den zeroing in one launch
    convert_all<<<TOT_CH / 256, 256>>>(q, k, v, Wq, Wk, Wv, Wo);

    // K, V projections (merged launch, 128x128 tiles) -> fp16 Kph/Vph
    dim3 kvGrid(DD / 128, MTOT / 128, 2);   // (8, 64, 2)
    hgemm_kv<<<kvGrid, 256, SMEM_KV>>>();

    // num/den over Kph, Vph
    dim3 redGrid(DD / 256, TT / 16);        // (4, 128)
    reduce_kernel<<<redGrid, 128>>>();

    // Q projection + fused sigmoid*num/den epilogue -> Yt (fp16), 64x128 tiles
    dim3 qoGrid(DD / 128, MTOT / 64);       // (8, 128)
    hgemm_qo<1><<<qoGrid, 256, SMEM_QO>>>(nullptr);

    // out = Yt @ Wo^T
    hgemm_qo<2><<<qoGrid, 256, SMEM_QO>>>(out);
}

// round 16
// speedup vs baseline: 1.0702x; 1.0149x over previous
#include <cuda_runtime.h>
#include <cuda_fp16.h>
#include <cstdint>

// AFT-Full simplified: exp_pos_bias == 1  =>  num/den are per-(b,d) sums over t.
// out = ( sigmoid(q@WqT) * num/den ) @ WoT
// GEMMs: legacy mma.sync fp16 single-term, XOR-swizzled smem, BK=64.
// This round: KV projections FUSED with the num/den reduction. Each CTA's
// M-tile gathers 4 batches x 16 t's, computes Kp AND Vp tiles, stages fp32
// accs to smem, reduces exp/num/den in-CTA (batch-max is tile-local).
// Kp/Vp never touch global memory; reduce_kernel eliminated.

#define BB 4
#define TT 2048
#define DD 1024
#define MTOT (BB * TT)   // 8192
#define KD 1024

// ---------------- scratch (static device globals) ----------------
__device__ __half g_qh[MTOT * KD];
__device__ __half g_kh[MTOT * KD];
__device__ __half g_vh[MTOT * KD];
__device__ __half g_Wqh[DD * KD], g_Wkh[DD * KD], g_Wvh[DD * KD], g_Woh[DD * KD];
__device__ __half g_Yth[MTOT * DD];
__device__ float g_num[BB * DD];
__device__ float g_den[BB * DD];

// ---------------- merged fp32 -> fp16 convert, all 7 tensors ----------------
constexpr int ACT_CH = MTOT * KD / 16;   // 524288 chunks of 16 floats
constexpr int W_CH   = DD * KD / 16;     // 65536
constexpr int TOT_CH = 3 * ACT_CH + 4 * W_CH;

__global__ __launch_bounds__(256) void convert_all(
    const float* __restrict__ q, const float* __restrict__ k, const float* __restrict__ v,
    const float* __restrict__ wq, const float* __restrict__ wk,
    const float* __restrict__ wv, const float* __restrict__ wo)
{
    const int i = blockIdx.x * blockDim.x + threadIdx.x;

    if (i < BB * DD) { g_num[i] = 0.0f; g_den[i] = 0.0f; }

    const float* src;
    __half* dst;
    size_t off;
    if (i < ACT_CH)              { src = q;  dst = g_qh;  off = i; }
    else if (i < 2 * ACT_CH)     { src = k;  dst = g_kh;  off = i - ACT_CH; }
    else if (i < 3 * ACT_CH)     { src = v;  dst = g_vh;  off = i - 2 * ACT_CH; }
    else {
        int w = i - 3 * ACT_CH;
        int t = w >> 16;
        off = w & 65535;
        if (t == 0)      { src = wq; dst = g_Wqh; }
        else if (t == 1) { src = wk; dst = g_Wkh; }
        else if (t == 2) { src = wv; dst = g_Wvh; }
        else             { src = wo; dst = g_Woh; }
    }

    const float4* s4 = (const float4*)(src) + off * 4;
    float4 x0 = s4[0], x1 = s4[1], x2 = s4[2], x3 = s4[3];
    float xs[16] = {x0.x, x0.y, x0.z, x0.w, x1.x, x1.y, x1.z, x1.w,
                    x2.x, x2.y, x2.z, x2.w, x3.x, x3.y, x3.z, x3.w};
    __half h[16];
#pragma unroll
    for (int j = 0; j < 16; j++) h[j] = __float2half(xs[j]);
    uint4* d4 = (uint4*)(dst + off * 16);
    d4[0] = *(uint4*)(h);
    d4[1] = *(uint4*)(h + 8);
}

// ---------------- PTX helpers ----------------
__device__ __forceinline__ void ldsm_x4(uint32_t& r0, uint32_t& r1, uint32_t& r2, uint32_t& r3, uint32_t addr) {
    asm volatile("ldmatrix.sync.aligned.m8n8.x4.shared.b16 {%0,%1,%2,%3}, [%4];"
                 : "=r"(r0), "=r"(r1), "=r"(r2), "=r"(r3) : "r"(addr));
}
__device__ __forceinline__ void mma_f16(float* d, const uint32_t* a, const uint32_t* b) {
    asm volatile("mma.sync.aligned.m16n8k16.row.col.f32.f16.f16.f32 "
                 "{%0,%1,%2,%3}, {%4,%5,%6,%7}, {%8,%9}, {%0,%1,%2,%3};"
                 : "+f"(d[0]), "+f"(d[1]), "+f"(d[2]), "+f"(d[3])
                 : "r"(a[0]), "r"(a[1]), "r"(a[2]), "r"(a[3]), "r"(b[0]), "r"(b[1]));
}
__device__ __forceinline__ void cp16(uint32_t s, const void* g) {
    asm volatile("cp.async.cg.shared.global [%0], [%1], 16;" :: "r"(s), "l"(g));
}
__device__ __forceinline__ void cp_commit() {
    asm volatile("cp.async.commit_group;" ::: "memory");
}
template <int N>
__device__ __forceinline__ void cp_wait() {
    asm volatile("cp.async.wait_group %0;" :: "n"(N) : "memory");
}

constexpr int BK = 64;
constexpr int NT = KD / BK;              // 16 k-tiles

// ======= Fused KV GEMM + reduction: 64(gathered)x128 tiles, 2 CTA/SM =======
// M-tile: local row r = b*16 + tl -> global row b*2048 + t0 + tl.
// Computes Kp and Vp tiles (fp32 acc), stages to smem, reduces num/den.
constexpr int AKV_T = 64 * BK * 2;        // 8192 B per A array
constexpr int BKV_T = 128 * BK * 2;       // 16384 B per B array
constexpr int STGKV = 2 * AKV_T + 2 * BKV_T;  // 49152 B (Ak, Av, Bk, Bv)
constexpr int SMEM_KV = 2 * STGKV;        // 98304 B (2-stage)
// reduction staging (reuses pipeline smem): 2 x 64 x 130 fp32 = 66560 B <= 98304

__global__ __launch_bounds__(256, 2) void hgemm_kvr()
{
    extern __shared__ char smem[];
    const uint32_t sb = (uint32_t)__cvta_generic_to_shared(smem);

    const int tid = threadIdx.x;
    const int wid = tid >> 5, lane = tid & 31;
    const int t0 = blockIdx.y * 16;
    const int colBase = blockIdx.x * 128;

    // 8 warps: 2 (M) x 4 (N); warp tile 32x32 per output matrix
    const int warpM = (wid >> 2) * 32;
    const int warpN = (wid & 3) * 32;

    const int aRowL = warpM + (lane & 15);
    const int aC16  = (lane >> 4);
    const int bRowL = warpN + ((lane >> 4) << 3) + (lane & 7);
    const int bC16  = ((lane >> 3) & 1);

    float accK[2][4][4], accV[2][4][4];
#pragma unroll
    for (int m = 0; m < 2; m++)
#pragma unroll
        for (int n = 0; n < 4; n++)
#pragma unroll
            for (int r = 0; r < 4; r++) { accK[m][n][r] = 0.0f; accV[m][n][r] = 0.0f; }

    auto fill_stage = [&](int buf, int k0) {
        const uint32_t stg = sb + buf * STGKV;
        // A_k and A_v: 512 chunks each; gathered rows
#pragma unroll
        for (int i = 0; i < 2; i++) {
            const int ch = tid + i * 256;
            const int r = ch >> 3, c = ch & 7;
            const int grow = (r >> 4) * TT + t0 + (r & 15);
            const uint32_t so = (uint32_t)(r * 128 + ((c ^ (r & 7)) * 16));
            const size_t go = (size_t)grow * KD + k0 + c * 8;
            cp16(stg + so, g_kh + go);
            cp16(stg + AKV_T + so, g_vh + go);
        }
        // B_k and B_v: 1024 chunks each
#pragma unroll
        for (int i = 0; i < 4; i++) {
            const int ch = tid + i * 256;
            const int r = ch >> 3, c = ch & 7;
            const uint32_t so = (uint32_t)(r * 128 + ((c ^ (r & 7)) * 16));
            const size_t go = (size_t)(colBase + r) * KD + k0 + c * 8;
            cp16(stg + 2 * AKV_T + so, g_Wkh + go);
            cp16(stg + 2 * AKV_T + BKV_T + so, g_Wvh + go);
        }
        cp_commit();
    };

    fill_stage(0, 0);
    fill_stage(1, BK);

    for (int kt = 0; kt < NT; kt++) {
        if (kt < NT - 1) cp_wait<1>(); else cp_wait<0>();
        __syncthreads();

        const uint32_t stg = sb + (kt & 1) * STGKV;
        const uint32_t sAk = stg;
        const uint32_t sAv = stg + AKV_T;
        const uint32_t sBk = stg + 2 * AKV_T;
        const uint32_t sBv = stg + 2 * AKV_T + BKV_T;

#pragma unroll
        for (int s = 0; s < 4; s++) {   // four k16 sub-steps per BK=64
            uint32_t a[2][4], b[4][2];
            // --- K ---
#pragma unroll
            for (int p = 0; p < 2; p++) {
                const int row = bRowL + p * 16;
                const int c16 = (s * 2 + bC16) ^ (row & 7);
                ldsm_x4(b[2 * p][0], b[2 * p][1], b[2 * p + 1][0], b[2 * p + 1][1],
                        sBk + (uint32_t)(row * 128 + c16 * 16));
            }
#pragma unroll
            for (int mf = 0; mf < 2; mf++) {
                const int row = aRowL + mf * 16;
                const int c16 = (s * 2 + aC16) ^ (row & 7);
                ldsm_x4(a[mf][0], a[mf][1], a[mf][2], a[mf][3],
                        sAk + (uint32_t)(row * 128 + c16 * 16));
            }
#pragma unroll
            for (int m = 0; m < 2; m++)
#pragma unroll
                for (int n = 0; n < 4; n++)
                    mma_f16(accK[m][n], a[m], b[n]);
            // --- V ---
#pragma unroll
            for (int p = 0; p < 2; p++) {
                const int row = bRowL + p * 16;
                const int c16 = (s * 2 + bC16) ^ (row & 7);
                ldsm_x4(b[2 * p][0], b[2 * p][1], b[2 * p + 1][0], b[2 * p + 1][1],
                        sBv + (uint32_t)(row * 128 + c16 * 16));
            }
#pragma unroll
            for (int mf = 0; mf < 2; mf++) {
                const int row = aRowL + mf * 16;
                const int c16 = (s * 2 + aC16) ^ (row & 7);
                ldsm_x4(a[mf][0], a[mf][1], a[mf][2], a[mf][3],
                        sAv + (uint32_t)(row * 128 + c16 * 16));
            }
#pragma unroll
            for (int m = 0; m < 2; m++)
#pragma unroll
                for (int n = 0; n < 4; n++)
                    mma_f16(accV[m][n], a[m], b[n]);
        }
        __syncthreads();   // all reads done before refill overwrites this buffer

        if (kt + 2 < NT) fill_stage(kt & 1, (kt + 2) * BK);
    }

    // ---------------- stage fp32 tiles to smem ----------------
    __syncthreads();   // pipeline smem free to reuse
    float* sK = (float*)smem;              // [64][130]
    float* sV = sK + 64 * 130;

    const int erL = warpM + (lane >> 2);
    const int ecL = warpN + (lane & 3) * 2;
#pragma unroll
    for (int m = 0; m < 2; m++)
#pragma unroll
        for (int n = 0; n < 4; n++) {
            const int c = ecL + n * 8;
#pragma unroll
            for (int h = 0; h < 2; h++) {
                const int r = erL + m * 16 + h * 8;
                sK[r * 130 + c]     = accK[m][n][h * 2];
                sK[r * 130 + c + 1] = accK[m][n][h * 2 + 1];
                sV[r * 130 + c]     = accV[m][n][h * 2];
                sV[r * 130 + c + 1] = accV[m][n][h * 2 + 1];
            }
        }
    __syncthreads();

    // ---------------- in-CTA num/den reduction ----------------
    // thread: d = tid&127 (column), th = tid>>7 selects 8 of the 16 t's
    {
        const int d  = tid & 127;
        const int th = tid >> 7;
        float num[BB] = {0.f, 0.f, 0.f, 0.f};
        float den[BB] = {0.f, 0.f, 0.f, 0.f};
#pragma unroll
        for (int t = th * 8; t < th * 8 + 8; t++) {
            float kk[BB];
#pragma unroll
            for (int b = 0; b < BB; b++) kk[b] = sK[(b * 16 + t) * 130 + d];
            const float mx = fmaxf(fmaxf(kk[0], kk[1]), fmaxf(kk[2], kk[3]));
#pragma unroll
            for (int b = 0; b < BB; b++) {
                const float e = __expf(kk[b] - mx);
                num[b] = fmaf(e, sV[(b * 16 + t) * 130 + d], num[b]);
                den[b] += e;
            }
        }
#pragma unroll
        for (int b = 0; b < BB; b++) {
            atomicAdd(&g_num[b * DD + colBase + d], num[b]);
            atomicAdd(&g_den[b * DD + colBase + d], den[b]);
        }
    }
}

// =============== Q/O GEMM: 64x128, 32x32 warps, 3 CTA/SM ===============
constexpr int A_T64 = 64 * BK * 2;       // 8192 B
constexpr int B_T64 = 128 * BK * 2;      // 16384 B
constexpr int STG64 = A_T64 + B_T64;     // 24576 B
constexpr int SMEM_QO = 3 * STG64;       // 73728 B

// MODE 1: Q + fused sigmoid*ratio -> g_Yth (fp16). MODE 2: out = Yt@Wo^T -> fp32.
template <int MODE>
__global__ __launch_bounds__(256, 3) void hgemm_qo(float* __restrict__ Cout)
{
    extern __shared__ char smem[];
    const uint32_t sb = (uint32_t)__cvta_generic_to_shared(smem);

    const __half* A  = (MODE == 1) ? g_qh  : g_Yth;
    const __half* Bh = (MODE == 1) ? g_Wqh : g_Woh;

    const int tid = threadIdx.x;
    const int wid = tid >> 5, lane = tid & 31;
    const int rowBase = blockIdx.y * 64;
    const int colBase = blockIdx.x * 128;

    const int warpM = (wid >> 2) * 32;
    const int warpN = (wid & 3) * 32;

    const int aRowL = warpM + (lane & 15);
    const int aC16  = (lane >> 4);
    const int bRowL = warpN + ((lane >> 4) << 3) + (lane & 7);
    const int bC16  = ((lane >> 3) & 1);

    float acc[2][4][4];
#pragma unroll
    for (int m = 0; m < 2; m++)
#pragma unroll
        for (int n = 0; n < 4; n++)
#pragma unroll
            for (int r = 0; r < 4; r++) acc[m][n][r] = 0.0f;

    auto fill_stage = [&](int buf, int k0) {
        const uint32_t stg = sb + buf * STG64;
#pragma unroll
        for (int i = 0; i < 2; i++) {
            const int ch = tid + i * 256;
            const int r = ch >> 3, c = ch & 7;
            const uint32_t so = (uint32_t)(r * 128 + ((c ^ (r & 7)) * 16));
            cp16(stg + so, A + (size_t)(rowBase + r) * KD + k0 + c * 8);
        }
#pragma unroll
        for (int i = 0; i < 4; i++) {
            const int ch = tid + i * 256;
            const int r = ch >> 3, c = ch & 7;
            const uint32_t so = (uint32_t)(r * 128 + ((c ^ (r & 7)) * 16));
            cp16(stg + A_T64 + so, Bh + (size_t)(colBase + r) * KD + k0 + c * 8);
        }
        cp_commit();
    };

    fill_stage(0, 0);
    fill_stage(1, BK);

    for (int kt = 0; kt < NT; kt++) {
        if (kt < NT - 1) cp_wait<1>(); else cp_wait<0>();
        __syncthreads();   // single barrier per iteration (3-stage)

        if (kt + 2 < NT) fill_stage((kt + 2) % 3, (kt + 2) * BK);

        const uint32_t stg = sb + (kt % 3) * STG64;
        const uint32_t sA = stg;
        const uint32_t sB = stg + A_T64;

#pragma unroll
        for (int s = 0; s < 4; s++) {
            uint32_t a[2][4], b[4][2];
#pragma unroll
            for (int p = 0; p < 2; p++) {
                const int row = bRowL + p * 16;
                const int c16 = (s * 2 + bC16) ^ (row & 7);
                ldsm_x4(b[2 * p][0], b[2 * p][1], b[2 * p + 1][0], b[2 * p + 1][1],
                        sB + (uint32_t)(row * 128 + c16 * 16));
            }
#pragma unroll
            for (int mf = 0; mf < 2; mf++) {
                const int row = aRowL + mf * 16;
                const int c16 = (s * 2 + aC16) ^ (row & 7);
                ldsm_x4(a[mf][0], a[mf][1], a[mf][2], a[mf][3],
                        sA + (uint32_t)(row * 128 + c16 * 16));
            }
#pragma unroll
            for (int m = 0; m < 2; m++)
#pragma unroll
                for (int n = 0; n < 4; n++)
                    mma_f16(acc[m][n], a[m], b[n]);
        }
    }

    const int er = rowBase + warpM + (lane >> 2);
    const int ec = colBase + warpN + (lane & 3) * 2;

    if (MODE == 1) {
        const int b = rowBase >> 11;
#pragma unroll
        for (int n = 0; n < 4; n++) {
            const int c = ec + n * 8;
            const float r0 = g_num[b * DD + c]     / g_den[b * DD + c];
            const float r1 = g_num[b * DD + c + 1] / g_den[b * DD + c + 1];
#pragma unroll
            for (int m = 0; m < 2; m++) {
#pragma unroll
                for (int h = 0; h < 2; h++) {
                    const int r = er + m * 16 + h * 8;
                    float y0 = r0 / (1.0f + __expf(-acc[m][n][h * 2]));
                    float y1 = r1 / (1.0f + __expf(-acc[m][n][h * 2 + 1]));
                    *(__half2*)(g_Yth + (size_t)r * DD + c) =
                        __floats2half2_rn(y0, y1);
                }
            }
        }
    } else {
#pragma unroll
        for (int m = 0; m < 2; m++)
#pragma unroll
            for (int n = 0; n < 4; n++) {
                const int c = ec + n * 8;
#pragma unroll
                for (int h = 0; h < 2; h++) {
                    const int r = er + m * 16 + h * 8;
                    *(float2*)(Cout + (size_t)r * DD + c) =
                        make_float2(acc[m][n][h * 2], acc[m][n][h * 2 + 1]);
                }
            }
    }
}

// ---------------------------------------------------------------------------
extern "C" void kernel_launch(void* const* d_in, const int* in_sizes, int n_in,
                              void* d_out, int out_size) {
    const float* q  = (const float*)d_in[0];
    const float* k  = (const float*)d_in[1];
    const float* v  = (const float*)d_in[2];
    const float* Wq = (const float*)d_in[3];
    const float* Wk = (const float*)d_in[4];
    const float* Wv = (const float*)d_in[5];
    const float* Wo = (const float*)d_in[6];
    // d_in[7] = W_bias: provably unused (exp(pos_bias - pos_bias) == 1)
    float* out = (float*)d_out;

    cudaFuncSetAttribute(hgemm_kvr,   cudaFuncAttributeMaxDynamicSharedMemorySize, SMEM_KV);
    cudaFuncSetAttribute(hgemm_qo<1>, cudaFuncAttributeMaxDynamicSharedMemorySize, SMEM_QO);
    cudaFuncSetAttribute(hgemm_qo<2>, cudaFuncAttributeMaxDynamicSharedMemorySize, SMEM_QO);

    // all converts + num/den zeroing in one launch
    convert_all<<<TOT_CH / 256, 256>>>(q, k, v, Wq, Wk, Wv, Wo);

    // Fused K/V projections + num/den reduction (Kp/Vp never hit gmem)
    dim3 kvGrid(DD / 128, TT / 16);         // (8, 128)
    hgemm_kvr<<<kvGrid, 256, SMEM_KV>>>();

    // Q projection + fused sigmoid*num/den epilogue -> Yt (fp16)
    dim3 qoGrid(DD / 128, MTOT / 64);       // (8, 128)
    hgemm_qo<1><<<qoGrid, 256, SMEM_QO>>>(nullptr);

    // out = Yt @ Wo^T
    hgemm_qo<2><<<qoGrid, 256, SMEM_QO>>>(out);
}

// round 17
// speedup vs baseline: 1.0714x; 1.0011x over previous
#include <cuda_runtime.h>
#include <cuda_fp16.h>
#include <cstdint>

// AFT-Full simplified: exp_pos_bias == 1  =>  num/den are per-(b,d) sums over t.
// out = ( sigmoid(q@WqT) * num/den ) @ WoT
// GEMMs: legacy mma.sync fp16 single-term, XOR-swizzled smem, BK=64.
// KV projections fused with num/den reduction (gathered 4-batch x 16-t M-tiles,
// fp32 accs staged to smem, in-CTA exp/num/den). This round: K+V ldsm issued
// together (8 ldsm -> 16 MMA per substep) for deeper MMA runs.

#define BB 4
#define TT 2048
#define DD 1024
#define MTOT (BB * TT)   // 8192
#define KD 1024

// ---------------- scratch (static device globals) ----------------
__device__ __half g_qh[MTOT * KD];
__device__ __half g_kh[MTOT * KD];
__device__ __half g_vh[MTOT * KD];
__device__ __half g_Wqh[DD * KD], g_Wkh[DD * KD], g_Wvh[DD * KD], g_Woh[DD * KD];
__device__ __half g_Yth[MTOT * DD];
__device__ float g_num[BB * DD];
__device__ float g_den[BB * DD];

// ---------------- merged fp32 -> fp16 convert, all 7 tensors ----------------
constexpr int ACT_CH = MTOT * KD / 16;   // 524288 chunks of 16 floats
constexpr int W_CH   = DD * KD / 16;     // 65536
constexpr int TOT_CH = 3 * ACT_CH + 4 * W_CH;

__global__ __launch_bounds__(256) void convert_all(
    const float* __restrict__ q, const float* __restrict__ k, const float* __restrict__ v,
    const float* __restrict__ wq, const float* __restrict__ wk,
    const float* __restrict__ wv, const float* __restrict__ wo)
{
    const int i = blockIdx.x * blockDim.x + threadIdx.x;

    if (i < BB * DD) { g_num[i] = 0.0f; g_den[i] = 0.0f; }

    const float* src;
    __half* dst;
    size_t off;
    if (i < ACT_CH)              { src = q;  dst = g_qh;  off = i; }
    else if (i < 2 * ACT_CH)     { src = k;  dst = g_kh;  off = i - ACT_CH; }
    else if (i < 3 * ACT_CH)     { src = v;  dst = g_vh;  off = i - 2 * ACT_CH; }
    else {
        int w = i - 3 * ACT_CH;
        int t = w >> 16;
        off = w & 65535;
        if (t == 0)      { src = wq; dst = g_Wqh; }
        else if (t == 1) { src = wk; dst = g_Wkh; }
        else if (t == 2) { src = wv; dst = g_Wvh; }
        else             { src = wo; dst = g_Woh; }
    }

    const float4* s4 = (const float4*)(src) + off * 4;
    float4 x0 = s4[0], x1 = s4[1], x2 = s4[2], x3 = s4[3];
    float xs[16] = {x0.x, x0.y, x0.z, x0.w, x1.x, x1.y, x1.z, x1.w,
                    x2.x, x2.y, x2.z, x2.w, x3.x, x3.y, x3.z, x3.w};
    __half h[16];
#pragma unroll
    for (int j = 0; j < 16; j++) h[j] = __float2half(xs[j]);
    uint4* d4 = (uint4*)(dst + off * 16);
    d4[0] = *(uint4*)(h);
    d4[1] = *(uint4*)(h + 8);
}

// ---------------- PTX helpers ----------------
__device__ __forceinline__ void ldsm_x4(uint32_t& r0, uint32_t& r1, uint32_t& r2, uint32_t& r3, uint32_t addr) {
    asm volatile("ldmatrix.sync.aligned.m8n8.x4.shared.b16 {%0,%1,%2,%3}, [%4];"
                 : "=r"(r0), "=r"(r1), "=r"(r2), "=r"(r3) : "r"(addr));
}
__device__ __forceinline__ void mma_f16(float* d, const uint32_t* a, const uint32_t* b) {
    asm volatile("mma.sync.aligned.m16n8k16.row.col.f32.f16.f16.f32 "
                 "{%0,%1,%2,%3}, {%4,%5,%6,%7}, {%8,%9}, {%0,%1,%2,%3};"
                 : "+f"(d[0]), "+f"(d[1]), "+f"(d[2]), "+f"(d[3])
                 : "r"(a[0]), "r"(a[1]), "r"(a[2]), "r"(a[3]), "r"(b[0]), "r"(b[1]));
}
__device__ __forceinline__ void cp16(uint32_t s, const void* g) {
    asm volatile("cp.async.cg.shared.global [%0], [%1], 16;" :: "r"(s), "l"(g));
}
__device__ __forceinline__ void cp_commit() {
    asm volatile("cp.async.commit_group;" ::: "memory");
}
template <int N>
__device__ __forceinline__ void cp_wait() {
    asm volatile("cp.async.wait_group %0;" :: "n"(N) : "memory");
}

constexpr int BK = 64;
constexpr int NT = KD / BK;              // 16 k-tiles

// ======= Fused KV GEMM + reduction: 64(gathered)x128 tiles, 2 CTA/SM =======
constexpr int AKV_T = 64 * BK * 2;        // 8192 B per A array
constexpr int BKV_T = 128 * BK * 2;       // 16384 B per B array
constexpr int STGKV = 2 * AKV_T + 2 * BKV_T;  // 49152 B (Ak, Av, Bk, Bv)
constexpr int SMEM_KV = 2 * STGKV;        // 98304 B (2-stage)

__global__ __launch_bounds__(256, 2) void hgemm_kvr()
{
    extern __shared__ char smem[];
    const uint32_t sb = (uint32_t)__cvta_generic_to_shared(smem);

    const int tid = threadIdx.x;
    const int wid = tid >> 5, lane = tid & 31;
    const int t0 = blockIdx.y * 16;
    const int colBase = blockIdx.x * 128;

    const int warpM = (wid >> 2) * 32;
    const int warpN = (wid & 3) * 32;

    const int aRowL = warpM + (lane & 15);
    const int aC16  = (lane >> 4);
    const int bRowL = warpN + ((lane >> 4) << 3) + (lane & 7);
    const int bC16  = ((lane >> 3) & 1);

    float accK[2][4][4], accV[2][4][4];
#pragma unroll
    for (int m = 0; m < 2; m++)
#pragma unroll
        for (int n = 0; n < 4; n++)
#pragma unroll
            for (int r = 0; r < 4; r++) { accK[m][n][r] = 0.0f; accV[m][n][r] = 0.0f; }

    auto fill_stage = [&](int buf, int k0) {
        const uint32_t stg = sb + buf * STGKV;
#pragma unroll
        for (int i = 0; i < 2; i++) {
            const int ch = tid + i * 256;
            const int r = ch >> 3, c = ch & 7;
            const int grow = (r >> 4) * TT + t0 + (r & 15);
            const uint32_t so = (uint32_t)(r * 128 + ((c ^ (r & 7)) * 16));
            const size_t go = (size_t)grow * KD + k0 + c * 8;
            cp16(stg + so, g_kh + go);
            cp16(stg + AKV_T + so, g_vh + go);
        }
#pragma unroll
        for (int i = 0; i < 4; i++) {
            const int ch = tid + i * 256;
            const int r = ch >> 3, c = ch & 7;
            const uint32_t so = (uint32_t)(r * 128 + ((c ^ (r & 7)) * 16));
            const size_t go = (size_t)(colBase + r) * KD + k0 + c * 8;
            cp16(stg + 2 * AKV_T + so, g_Wkh + go);
            cp16(stg + 2 * AKV_T + BKV_T + so, g_Wvh + go);
        }
        cp_commit();
    };

    fill_stage(0, 0);
    fill_stage(1, BK);

    for (int kt = 0; kt < NT; kt++) {
        if (kt < NT - 1) cp_wait<1>(); else cp_wait<0>();
        __syncthreads();

        const uint32_t stg = sb + (kt & 1) * STGKV;
        const uint32_t sAk = stg;
        const uint32_t sAv = stg + AKV_T;
        const uint32_t sBk = stg + 2 * AKV_T;
        const uint32_t sBv = stg + 2 * AKV_T + BKV_T;

#pragma unroll
        for (int s = 0; s < 4; s++) {   // four k16 sub-steps per BK=64
            // ---- issue ALL 8 ldsm (K and V) before any MMA: 16-MMA runs
            uint32_t aK[2][4], bK[4][2], aV[2][4], bV[4][2];
#pragma unroll
            for (int p = 0; p < 2; p++) {
                const int row = bRowL + p * 16;
                const int c16 = (s * 2 + bC16) ^ (row & 7);
                const uint32_t off = (uint32_t)(row * 128 + c16 * 16);
                ldsm_x4(bK[2 * p][0], bK[2 * p][1], bK[2 * p + 1][0], bK[2 * p + 1][1], sBk + off);
                ldsm_x4(bV[2 * p][0], bV[2 * p][1], bV[2 * p + 1][0], bV[2 * p + 1][1], sBv + off);
            }
#pragma unroll
            for (int mf = 0; mf < 2; mf++) {
                const int row = aRowL + mf * 16;
                const int c16 = (s * 2 + aC16) ^ (row & 7);
                const uint32_t off = (uint32_t)(row * 128 + c16 * 16);
                ldsm_x4(aK[mf][0], aK[mf][1], aK[mf][2], aK[mf][3], sAk + off);
                ldsm_x4(aV[mf][0], aV[mf][1], aV[mf][2], aV[mf][3], sAv + off);
            }
#pragma unroll
            for (int m = 0; m < 2; m++)
#pragma unroll
                for (int n = 0; n < 4; n++)
                    mma_f16(accK[m][n], aK[m], bK[n]);
#pragma unroll
            for (int m = 0; m < 2; m++)
#pragma unroll
                for (int n = 0; n < 4; n++)
                    mma_f16(accV[m][n], aV[m], bV[n]);
        }
        __syncthreads();   // all reads done before refill overwrites this buffer

        if (kt + 2 < NT) fill_stage(kt & 1, (kt + 2) * BK);
    }

    // ---------------- stage fp32 tiles to smem ----------------
    __syncthreads();
    float* sK = (float*)smem;              // [64][130]
    float* sV = sK + 64 * 130;

    const int erL = warpM + (lane >> 2);
    const int ecL = warpN + (lane & 3) * 2;
#pragma unroll
    for (int m = 0; m < 2; m++)
#pragma unroll
        for (int n = 0; n < 4; n++) {
            const int c = ecL + n * 8;
#pragma unroll
            for (int h = 0; h < 2; h++) {
                const int r = erL + m * 16 + h * 8;
                sK[r * 130 + c]     = accK[m][n][h * 2];
                sK[r * 130 + c + 1] = accK[m][n][h * 2 + 1];
                sV[r * 130 + c]     = accV[m][n][h * 2];
                sV[r * 130 + c + 1] = accV[m][n][h * 2 + 1];
            }
        }
    __syncthreads();

    // ---------------- in-CTA num/den reduction ----------------
    {
        const int d  = tid & 127;
        const int th = tid >> 7;
        float num[BB] = {0.f, 0.f, 0.f, 0.f};
        float den[BB] = {0.f, 0.f, 0.f, 0.f};
#pragma unroll
        for (int t = th * 8; t < th * 8 + 8; t++) {
            float kk[BB];
#pragma unroll
            for (int b = 0; b < BB; b++) kk[b] = sK[(b * 16 + t) * 130 + d];
            const float mx = fmaxf(fmaxf(kk[0], kk[1]), fmaxf(kk[2], kk[3]));
#pragma unroll
            for (int b = 0; b < BB; b++) {
                const float e = __expf(kk[b] - mx);
                num[b] = fmaf(e, sV[(b * 16 + t) * 130 + d], num[b]);
                den[b] += e;
            }
        }
#pragma unroll
        for (int b = 0; b < BB; b++) {
            atomicAdd(&g_num[b * DD + colBase + d], num[b]);
            atomicAdd(&g_den[b * DD + colBase + d], den[b]);
        }
    }
}

// =============== Q/O GEMM: 64x128, 32x32 warps, 3 CTA/SM ===============
constexpr int A_T64 = 64 * BK * 2;       // 8192 B
constexpr int B_T64 = 128 * BK * 2;      // 16384 B
constexpr int STG64 = A_T64 + B_T64;     // 24576 B
constexpr int SMEM_QO = 3 * STG64;       // 73728 B

// MODE 1: Q + fused sigmoid*ratio -> g_Yth (fp16). MODE 2: out = Yt@Wo^T -> fp32.
template <int MODE>
__global__ __launch_bounds__(256, 3) void hgemm_qo(float* __restrict__ Cout)
{
    extern __shared__ char smem[];
    const uint32_t sb = (uint32_t)__cvta_generic_to_shared(smem);

    const __half* A  = (MODE == 1) ? g_qh  : g_Yth;
    const __half* Bh = (MODE == 1) ? g_Wqh : g_Woh;

    const int tid = threadIdx.x;
    const int wid = tid >> 5, lane = tid & 31;
    const int rowBase = blockIdx.y * 64;
    const int colBase = blockIdx.x * 128;

    const int warpM = (wid >> 2) * 32;
    const int warpN = (wid & 3) * 32;

    const int aRowL = warpM + (lane & 15);
    const int aC16  = (lane >> 4);
    const int bRowL = warpN + ((lane >> 4) << 3) + (lane & 7);
    const int bC16  = ((lane >> 3) & 1);

    float acc[2][4][4];
#pragma unroll
    for (int m = 0; m < 2; m++)
#pragma unroll
        for (int n = 0; n < 4; n++)
#pragma unroll
            for (int r = 0; r < 4; r++) acc[m][n][r] = 0.0f;

    auto fill_stage = [&](int buf, int k0) {
        const uint32_t stg = sb + buf * STG64;
#pragma unroll
        for (int i = 0; i < 2; i++) {
            const int ch = tid + i * 256;
            const int r = ch >> 3, c = ch & 7;
            const uint32_t so = (uint32_t)(r * 128 + ((c ^ (r & 7)) * 16));
            cp16(stg + so, A + (size_t)(rowBase + r) * KD + k0 + c * 8);
        }
#pragma unroll
        for (int i = 0; i < 4; i++) {
            const int ch = tid + i * 256;
            const int r = ch >> 3, c = ch & 7;
            const uint32_t so = (uint32_t)(r * 128 + ((c ^ (r & 7)) * 16));
            cp16(stg + A_T64 + so, Bh + (size_t)(colBase + r) * KD + k0 + c * 8);
        }
        cp_commit();
    };

    fill_stage(0, 0);
    fill_stage(1, BK);

    for (int kt = 0; kt < NT; kt++) {
        if (kt < NT - 1) cp_wait<1>(); else cp_wait<0>();
        __syncthreads();   // single barrier per iteration (3-stage)

        if (kt + 2 < NT) fill_stage((kt + 2) % 3, (kt + 2) * BK);

        const uint32_t stg = sb + (kt % 3) * STG64;
        const uint32_t sA = stg;
        const uint32_t sB = stg + A_T64;

#pragma unroll
        for (int s = 0; s < 4; s++) {
            uint32_t a[2][4], b[4][2];
#pragma unroll
            for (int p = 0; p < 2; p++) {
                const int row = bRowL + p * 16;
                const int c16 = (s * 2 + bC16) ^ (row & 7);
                ldsm_x4(b[2 * p][0], b[2 * p][1], b[2 * p + 1][0], b[2 * p + 1][1],
                        sB + (uint32_t)(row * 128 + c16 * 16));
            }
#pragma unroll
            for (int mf = 0; mf < 2; mf++) {
                const int row = aRowL + mf * 16;
                const int c16 = (s * 2 + aC16) ^ (row & 7);
                ldsm_x4(a[mf][0], a[mf][1], a[mf][2], a[mf][3],
                        sA + (uint32_t)(row * 128 + c16 * 16));
            }
#pragma unroll
            for (int m = 0; m < 2; m++)
#pragma unroll
                for (int n = 0; n < 4; n++)
                    mma_f16(acc[m][n], a[m], b[n]);
        }
    }

    const int er = rowBase + warpM + (lane >> 2);
    const int ec = colBase + warpN + (lane & 3) * 2;

    if (MODE == 1) {
        const int b = rowBase >> 11;
        // hoist all ratio loads above the store loop (one latency bubble, not 4)
        float rr[4][2];
#pragma unroll
        for (int n = 0; n < 4; n++) {
            const int c = ec + n * 8;
            rr[n][0] = g_num[b * DD + c]     / g_den[b * DD + c];
            rr[n][1] = g_num[b * DD + c + 1] / g_den[b * DD + c + 1];
        }
#pragma unroll
        for (int n = 0; n < 4; n++) {
            const int c = ec + n * 8;
#pragma unroll
            for (int m = 0; m < 2; m++) {
#pragma unroll
                for (int h = 0; h < 2; h++) {
                    const int r = er + m * 16 + h * 8;
                    float y0 = rr[n][0] / (1.0f + __expf(-acc[m][n][h * 2]));
                    float y1 = rr[n][1] / (1.0f + __expf(-acc[m][n][h * 2 + 1]));
                    *(__half2*)(g_Yth + (size_t)r * DD + c) =
                        __floats2half2_rn(y0, y1);
                }
            }
        }
    } else {
#pragma unroll
        for (int m = 0; m < 2; m++)
#pragma unroll
            for (int n = 0; n < 4; n++) {
                const int c = ec + n * 8;
#pragma unroll
                for (int h = 0; h < 2; h++) {
                    const int r = er + m * 16 + h * 8;
                    *(float2*)(Cout + (size_t)r * DD + c) =
                        make_float2(acc[m][n][h * 2], acc[m][n][h * 2 + 1]);
                }
            }
    }
}

// ---------------------------------------------------------------------------
extern "C" void kernel_launch(void* const* d_in, const int* in_sizes, int n_in,
                              void* d_out, int out_size) {
    const float* q  = (const float*)d_in[0];
    const float* k  = (const float*)d_in[1];
    const float* v  = (const float*)d_in[2];
    const float* Wq = (const float*)d_in[3];
    const float* Wk = (const float*)d_in[4];
    const float* Wv = (const float*)d_in[5];
    const float* Wo = (const float*)d_in[6];
    // d_in[7] = W_bias: provably unused (exp(pos_bias - pos_bias) == 1)
    float* out = (float*)d_out;

    cudaFuncSetAttribute(hgemm_kvr,   cudaFuncAttributeMaxDynamicSharedMemorySize, SMEM_KV);
    cudaFuncSetAttribute(hgemm_qo<1>, cudaFuncAttributeMaxDynamicSharedMemorySize, SMEM_QO);
    cudaFuncSetAttribute(hgemm_qo<2>, cudaFuncAttributeMaxDynamicSharedMemorySize, SMEM_QO);

    // all converts + num/den zeroing in one launch
    convert_all<<<TOT_CH / 256, 256>>>(q, k, v, Wq, Wk, Wv, Wo);

    // Fused K/V projections + num/den reduction (Kp/Vp never hit gmem)
    dim3 kvGrid(DD / 128, TT / 16);         // (8, 128)
    hgemm_kvr<<<kvGrid, 256, SMEM_KV>>>();

    // Q projection + fused sigmoid*num/den epilogue -> Yt (fp16)
    dim3 qoGrid(DD / 128, MTOT / 64);       // (8, 128)
    hgemm_qo<1><<<qoGrid, 256, SMEM_QO>>>(nullptr);

    // out = Yt @ Wo^T
    hgemm_qo<2><<<qoGrid, 256, SMEM_QO>>>(out);
}